// round 3
// baseline (speedup 1.0000x reference)
#include <cuda_runtime.h>
#include <cuda_bf16.h>

#define OUTF 32
#define N_MAX 100000
#define E_MAX 1600000
#define SCAN_CHUNK 1024            // elems per scan block
#define NB_MAX 128                 // >= ceil(N_MAX/SCAN_CHUNK) = 98

// Scratch (device globals: allocation-free, graph-capturable)
__device__ float g_h[N_MAX * OUTF];      // 12.8 MB: h = outdeg^-1/2 * (sparse feat @ W)
__device__ int   g_outdeg[N_MAX];
__device__ int   g_indeg [N_MAX];
__device__ int   g_off   [N_MAX];        // CSR row offsets (by dst)
__device__ int   g_cursor[N_MAX];        // scatter cursors (init = offsets)
__device__ int   g_ssrc  [E_MAX];        // src ids sorted by dst
__device__ int   g_bsums [NB_MAX];       // scan block sums
__device__ int   g_bscan [NB_MAX];       // exclusive scan of block sums

// ---------------------------------------------------------------------------
// K0: zero degree counters
__global__ void k_zero(int n_nodes) {
    int i = blockIdx.x * blockDim.x + threadIdx.x;
    int stride = gridDim.x * blockDim.x;
    for (int t = i; t < n_nodes; t += stride) { g_outdeg[t] = 0; g_indeg[t] = 0; }
}

// ---------------------------------------------------------------------------
// K1: out/in degree histograms (int4 vectorized)
__global__ void k_deg(const int* __restrict__ src, const int* __restrict__ dst, int n_edges) {
    int i = blockIdx.x * blockDim.x + threadIdx.x;
    int stride = gridDim.x * blockDim.x;
    int n4 = n_edges >> 2;
    const int4* src4 = (const int4*)src;
    const int4* dst4 = (const int4*)dst;
    for (int e = i; e < n4; e += stride) {
        int4 s = src4[e];
        int4 d = dst4[e];
        atomicAdd(&g_outdeg[s.x], 1); atomicAdd(&g_outdeg[s.y], 1);
        atomicAdd(&g_outdeg[s.z], 1); atomicAdd(&g_outdeg[s.w], 1);
        atomicAdd(&g_indeg [d.x], 1); atomicAdd(&g_indeg [d.y], 1);
        atomicAdd(&g_indeg [d.z], 1); atomicAdd(&g_indeg [d.w], 1);
    }
    for (int e = (n4 << 2) + i; e < n_edges; e += stride) {
        atomicAdd(&g_outdeg[src[e]], 1);
        atomicAdd(&g_indeg [dst[e]], 1);
    }
}

// ---------------------------------------------------------------------------
// Scan stage A: per-block sums of indeg (1024 elems / block, 256 threads x 4)
__global__ void k_scanA(int n_nodes) {
    __shared__ int ssum[256];
    int tid = threadIdx.x;
    int base = blockIdx.x * SCAN_CHUNK + tid * 4;
    int s = 0;
    #pragma unroll
    for (int k = 0; k < 4; k++) {
        int idx = base + k;
        if (idx < n_nodes) s += g_indeg[idx];
    }
    ssum[tid] = s;
    __syncthreads();
    for (int off = 128; off > 0; off >>= 1) {
        if (tid < off) ssum[tid] += ssum[tid + off];
        __syncthreads();
    }
    if (tid == 0) g_bsums[blockIdx.x] = ssum[0];
}

// Scan stage B: exclusive scan of block sums (single block)
__global__ void k_scanB(int nb) {
    __shared__ int sv[NB_MAX];
    int tid = threadIdx.x;             // 128 threads
    int v = (tid < nb) ? g_bsums[tid] : 0;
    sv[tid] = v;
    __syncthreads();
    for (int off = 1; off < NB_MAX; off <<= 1) {
        int t = (tid >= off) ? sv[tid - off] : 0;
        __syncthreads();
        sv[tid] += t;
        __syncthreads();
    }
    if (tid < nb) g_bscan[tid] = sv[tid] - v;   // exclusive
}

// Scan stage C: full exclusive offsets; also init cursors
__global__ void k_scanC(int n_nodes) {
    __shared__ int ssum[256];
    int tid = threadIdx.x;
    int base = blockIdx.x * SCAN_CHUNK + tid * 4;
    int v[4]; int tsum = 0;
    #pragma unroll
    for (int k = 0; k < 4; k++) {
        int idx = base + k;
        v[k] = (idx < n_nodes) ? g_indeg[idx] : 0;
        tsum += v[k];
    }
    ssum[tid] = tsum;
    __syncthreads();
    for (int off = 1; off < 256; off <<= 1) {
        int t = (tid >= off) ? ssum[tid - off] : 0;
        __syncthreads();
        ssum[tid] += t;
        __syncthreads();
    }
    int run = ssum[tid] - tsum + g_bscan[blockIdx.x];   // exclusive start for this thread
    #pragma unroll
    for (int k = 0; k < 4; k++) {
        int idx = base + k;
        if (idx < n_nodes) { g_off[idx] = run; g_cursor[idx] = run; }
        run += v[k];
    }
}

// ---------------------------------------------------------------------------
// K2: scatter src ids into dst-sorted order (counting sort placement)
__global__ void k_scatter(const int* __restrict__ src, const int* __restrict__ dst, int n_edges) {
    int i = blockIdx.x * blockDim.x + threadIdx.x;
    int stride = gridDim.x * blockDim.x;
    int n4 = n_edges >> 2;
    const int4* src4 = (const int4*)src;
    const int4* dst4 = (const int4*)dst;
    for (int e = i; e < n4; e += stride) {
        int4 s = src4[e];
        int4 d = dst4[e];
        g_ssrc[atomicAdd(&g_cursor[d.x], 1)] = s.x;
        g_ssrc[atomicAdd(&g_cursor[d.y], 1)] = s.y;
        g_ssrc[atomicAdd(&g_cursor[d.z], 1)] = s.z;
        g_ssrc[atomicAdd(&g_cursor[d.w], 1)] = s.w;
    }
    for (int e = (n4 << 2) + i; e < n_edges; e += stride) {
        g_ssrc[atomicAdd(&g_cursor[dst[e]], 1)] = src[e];
    }
}

// ---------------------------------------------------------------------------
// K3: h[n,c] = outdeg(n)^-1/2 * sum_j val[n,j] * W[idx[n,j], c]
// PERSISTENT: W staged into smem once per block; warp per node.
__global__ void k_feat(const float* __restrict__ vals, const int* __restrict__ idxs,
                       const float* __restrict__ W, int n_nodes, int in_feats, int kk) {
    extern __shared__ float sW[];
    for (int t = threadIdx.x; t < in_feats * OUTF; t += blockDim.x) sW[t] = W[t];
    __syncthreads();

    int lid   = threadIdx.x & 31;
    int wid   = threadIdx.x >> 5;
    int wpb   = blockDim.x >> 5;
    int gwid  = blockIdx.x * wpb + wid;
    int nwarp = gridDim.x * wpb;

    for (int node = gwid; node < n_nodes; node += nwarp) {
        float v  = vals[(long long)node * kk + lid];
        int   ix = idxs[(long long)node * kk + lid];

        float acc = 0.0f;
        #pragma unroll
        for (int j = 0; j < 32; j++) {
            float vj = __shfl_sync(0xffffffffu, v,  j);
            int   ij = __shfl_sync(0xffffffffu, ix, j);
            acc = fmaf(vj, sW[ij * OUTF + lid], acc);
        }

        float d = (float)g_outdeg[node];
        acc *= rsqrtf(fmaxf(d, 1.0f));
        g_h[node * OUTF + lid] = acc;
    }
}

// ---------------------------------------------------------------------------
// K4: atomic-free gather aggregation + fused normalize/bias.
// One warp per dst node; lane c owns channel c. Per edge: 1 coalesced 128B
// read of h[src]; accumulate in registers; single 128B store per node.
__global__ void k_gather(float* __restrict__ out, const float* __restrict__ bias, int n_nodes) {
    int lid  = threadIdx.x & 31;
    int wid  = threadIdx.x >> 5;
    int node = blockIdx.x * (blockDim.x >> 5) + wid;
    if (node >= n_nodes) return;

    float b   = bias[lid];
    int   beg = g_off[node];
    int   deg = g_indeg[node];

    float acc = 0.0f;
    for (int base = 0; base < deg; base += 32) {
        int rem = deg - base;
        int cnt = rem < 32 ? rem : 32;
        int s = (lid < cnt) ? g_ssrc[beg + base + lid] : 0;
        #pragma unroll 4
        for (int j = 0; j < cnt; j++) {
            int sj = __shfl_sync(0xffffffffu, s, j);
            acc += __ldg(&g_h[sj * OUTF + lid]);
        }
    }

    float r = rsqrtf(fmaxf((float)deg, 1.0f));
    out[node * OUTF + lid] = acc * r + b;
}

// ---------------------------------------------------------------------------
extern "C" void kernel_launch(void* const* d_in, const int* in_sizes, int n_in,
                              void* d_out, int out_size) {
    const float* vals = (const float*)d_in[0];   // topk_values [N,K]
    const int*   idxs = (const int*)  d_in[1];   // topk_indices [N,K]
    const int*   src  = (const int*)  d_in[2];   // [E]
    const int*   dst  = (const int*)  d_in[3];   // [E]
    const float* W    = (const float*)d_in[4];   // [in_feats, 32]
    const float* bias = (const float*)d_in[5];   // [32]
    float* out = (float*)d_out;

    int n_nodes  = out_size / OUTF;              // 100000
    int n_edges  = in_sizes[2];                  // 1600000
    int in_feats = in_sizes[4] / OUTF;           // 256
    int kk       = in_sizes[0] / n_nodes;        // 32

    int nb = (n_nodes + SCAN_CHUNK - 1) / SCAN_CHUNK;   // 98

    k_zero<<<256, 256>>>(n_nodes);
    k_deg <<<1024, 256>>>(src, dst, n_edges);

    k_scanA<<<nb, 256>>>(n_nodes);
    k_scanB<<<1, NB_MAX>>>(nb);
    k_scanC<<<nb, 256>>>(n_nodes);

    // k_feat only depends on k_deg (outdeg) — overlaps scan serialization cost
    size_t smem = (size_t)in_feats * OUTF * sizeof(float);   // 32 KB
    k_feat<<<592, 256, smem>>>(vals, idxs, W, n_nodes, in_feats, kk);

    k_scatter<<<1024, 256>>>(src, dst, n_edges);

    int gather_blocks = (n_nodes + 7) / 8;       // 8 warps (nodes) per block
    k_gather<<<gather_blocks, 256>>>(out, bias, n_nodes);
}